// round 6
// baseline (speedup 1.0000x reference)
#include <cuda_runtime.h>
#include <cstdint>

// Problem constants (from reference: B=1024, V=100000, C=1024)
#define C_CLUSTERS 1024
#define MAX_V      100352   // padded to multiple of 8

__device__ __align__(16) unsigned short g_idx16[MAX_V];           // compact index

// ---------------------------------------------------------------------------
// Pass 0: int32 cluster index -> uint16
// ---------------------------------------------------------------------------
__global__ void idx_convert_kernel(const int* __restrict__ idx, int V) {
    int i = blockIdx.x * blockDim.x + threadIdx.x;
    if (i < V) g_idx16[i] = (unsigned short)idx[i];
}

// ---------------------------------------------------------------------------
// Fused kernel: one block per row b.
//   Phase A: segment-sum of exp into smem (atomicAdd scatter)
//   log epilogue in-place in smem
//   Phase B: re-read row (L2-warm), out = x - s_d[c], cluster-0 -> log-sigmoid
// No global logdenom table; logits read twice but second read targets L2
// (296 resident rows x 400KB = 118MB < 126MB L2 at occupancy 2).
// ---------------------------------------------------------------------------
__global__ __launch_bounds__(512, 2)
void fused_kernel(const float* __restrict__ logits, float* __restrict__ out,
                  int V) {
    __shared__ float s_d[C_CLUSTERS];
    const int b   = blockIdx.x;
    const int tid = threadIdx.x;
    const int nt  = blockDim.x;

    for (int i = tid; i < C_CLUSTERS; i += nt) s_d[i] = 0.0f;
    __syncthreads();

    const float* row = logits + (size_t)b * V;
    const int V4 = V >> 2;
    const float4*  row4 = (const float4*)row;
    const ushort4* idx4 = (const ushort4*)g_idx16;

    // ---- Phase A: scatter-accumulate exp ----
    #pragma unroll 2
    for (int i = tid; i < V4; i += nt) {
        float4  x = row4[i];
        ushort4 c = idx4[i];
        atomicAdd(&s_d[c.x], __expf(x.x));
        atomicAdd(&s_d[c.y], __expf(x.y));
        atomicAdd(&s_d[c.z], __expf(x.z));
        atomicAdd(&s_d[c.w], __expf(x.w));
    }
    for (int i = (V4 << 2) + tid; i < V; i += nt) {     // tail (V % 4)
        atomicAdd(&s_d[g_idx16[i]], __expf(row[i]));
    }
    __syncthreads();

    // ---- log epilogue in place ----
    for (int i = tid; i < C_CLUSTERS; i += nt) {
        s_d[i] = logf(fmaxf(s_d[i], 1e-20f));           // SAFE_LOG_MIN clamp
    }
    __syncthreads();

    // ---- Phase B: streaming output ----
    float4* orow4 = (float4*)(out + (size_t)b * V);
    #pragma unroll 2
    for (int i = tid; i < V4; i += nt) {
        float4  x = row4[i];
        ushort4 c = idx4[i];
        float4 r;
        r.x = x.x - s_d[c.x];
        r.y = x.y - s_d[c.y];
        r.z = x.z - s_d[c.z];
        r.w = x.w - s_d[c.w];
        // log-sigmoid override for cluster 0 (~0.1% of elements):
        // branch at warp granularity so the MUFU-heavy path isn't predicated
        // onto every lane.
        bool need = (c.x == 0) | (c.y == 0) | (c.z == 0) | (c.w == 0);
        if (__any_sync(0xffffffffu, need)) {
            if (c.x == 0) r.x = x.x - log1pf(__expf(x.x));
            if (c.y == 0) r.y = x.y - log1pf(__expf(x.y));
            if (c.z == 0) r.z = x.z - log1pf(__expf(x.z));
            if (c.w == 0) r.w = x.w - log1pf(__expf(x.w));
        }
        orow4[i] = r;
    }
    {   // tail (V % 4)
        float* orow = out + (size_t)b * V;
        for (int i = (V4 << 2) + tid; i < V; i += nt) {
            float x = row[i];
            unsigned short c = g_idx16[i];
            orow[i] = (c == 0) ? (x - log1pf(__expf(x))) : (x - s_d[c]);
        }
    }
}

// ---------------------------------------------------------------------------
extern "C" void kernel_launch(void* const* d_in, const int* in_sizes, int n_in,
                              void* d_out, int out_size) {
    const float* logits = (const float*)d_in[0];
    const int*   cidx   = (const int*)d_in[1];   // int32 (JAX x64 disabled)
    const int V = in_sizes[1];
    const int B = in_sizes[0] / V;

    {   // Pass 0: index conversion (tiny)
        int threads = 256;
        int blocks  = (V + threads - 1) / threads;
        idx_convert_kernel<<<blocks, threads>>>(cidx, V);
    }

    // Fused segment-sum + output
    fused_kernel<<<B, 512>>>(logits, (float*)d_out, V);
}